// round 16
// baseline (speedup 1.0000x reference)
#include <cuda_runtime.h>
#include <cuda_bf16.h>

#define BB 8
#define NN 2048
#define NPAD (NN + 512)
#define BIGF 1e30f
#define FARF 1e15f

// shape: block = 128 thr; grid (GQ, RSPLIT, BB) = (8, 32, 8) = 2048 blocks
#define TB     128
#define GQ     8
#define RSPLIT 32
#define ARR    (GQ * RSPLIT)     // 256 arrivals per batch-task

// Scratch (allocation-free). Points transformed: (x+y, x-y, z, 0).
// g_valid[0]=clean(points+target), g_valid[1]=predp(points+pred)
__device__ __align__(16) float4       g_valid[2][BB][NPAD];
__device__ __align__(16) unsigned int g_minbits[2][BB][NN];  // [0]=row(clean) [1]=col(pred)
__device__ int          g_cnt[BB];
__device__ float        g_l1part[128];
__device__ float        g_tasksum[BB];
__device__ unsigned int g_done_task[BB];
__device__ unsigned int g_done;

// ---------------------------------------------------------------------------
// Kernel 1: prep — 128 blocks x 128 threads, one point per thread (unchanged).
// ---------------------------------------------------------------------------
__global__ void __launch_bounds__(128)
prep_kernel(const float* __restrict__ pred,
            const float* __restrict__ target,
            const int*   __restrict__ mask,
            const float* __restrict__ points) {
    int bid = blockIdx.x, tid = threadIdx.x;
    int b = bid >> 4, s = bid & 15;
    int n  = s * 128 + tid;
    int gi = b * NN + n;

    const float* pp = pred   + gi * 3;
    const float* tt = target + gi * 3;
    const float* xx = points + gi * 3;
    float p0 = pp[0], p1 = pp[1], p2 = pp[2];
    float t0 = tt[0], t1 = tt[1], t2 = tt[2];
    float x0 = xx[0], x1 = xx[1], x2 = xx[2];
    int m = mask[gi];

    const unsigned bigbits = __float_as_uint(BIGF);
    g_minbits[0][b][n] = bigbits;
    g_minbits[1][b][n] = bigbits;

    float c0 = x0 + t0, c1 = x1 + t1, c2 = x2 + t2;   // clean
    float q0 = x0 + p0, q1 = x1 + p1, q2 = x2 + p2;   // predp
    float l1 = 0.f;

    __shared__ int sh_cnt, sh_base;
    if (tid == 0) sh_cnt = 0;
    __syncthreads();
    int klocal = -1;
    if (m) {
        l1 = fabsf(p0 - t0) + fabsf(p1 - t1) + fabsf(p2 - t2);
        klocal = atomicAdd(&sh_cnt, 1);
    }
    __syncthreads();
    if (tid == 0) sh_base = atomicAdd(&g_cnt[b], sh_cnt);

    __shared__ float wsum[4];
#pragma unroll
    for (int o = 16; o > 0; o >>= 1) l1 += __shfl_down_sync(0xffffffffu, l1, o);
    if ((tid & 31) == 0) wsum[tid >> 5] = l1;
    __syncthreads();
    if (tid == 0)
        g_l1part[bid] = wsum[0] + wsum[1] + wsum[2] + wsum[3];

    if (m) {
        int k = sh_base + klocal;
        g_valid[0][b][k] = make_float4(c0 + c1, c0 - c1, c2, 0.f);
        g_valid[1][b][k] = make_float4(q0 + q1, q0 - q1, q2, 0.f);
    }
}

// ---------------------------------------------------------------------------
// Kernel 2: dual-direction chamfer. grid (8, 32, 8) = 2048 blocks, TB=128.
// Thread owns a query row (uniform smem tile broadcast, row-min in register).
// Col-min via __reduce_min_sync per tile-step; lane j owns ref j's register.
// |dx|+|dy|+|dz| == max(|du|,|dv|) + |dz| with (u,v) = (x+y, x-y).
// ---------------------------------------------------------------------------
__global__ void __launch_bounds__(TB)
chamfer_kernel(float* __restrict__ out) {
    int tid  = threadIdx.x, lane = tid & 31;
    int b    = blockIdx.z;
    int cnt  = g_cnt[b];

    int qn   = (cnt + GQ - 1) / GQ;            // <= 256
    int q_lo = blockIdx.x * qn;
    int q_hi = min(q_lo + qn, cnt);
    int rn   = (cnt + RSPLIT - 1) / RSPLIT;    // <= 64
    int r_lo = blockIdx.y * rn;
    int r_hi = min(r_lo + rn, cnt);

    __shared__ float4 tile[32];

    if (q_lo < cnt && r_lo < r_hi) {
        const float4* __restrict__ Q = g_valid[0][b];   // clean (rows)
        const float4* __restrict__ R = g_valid[1][b];   // pred  (cols)
        unsigned int* __restrict__ Mx = g_minbits[0][b];
        unsigned int* __restrict__ My = g_minbits[1][b];

        for (int g0 = r_lo; g0 < r_hi; g0 += 32) {      // 1 group typical
            __syncthreads();
            if (tid < 32) {
                int r = g0 + tid;
                tile[tid] = (r < r_hi) ? R[r]
                                       : make_float4(FARF, FARF, FARF, 0.f);
            }
            __syncthreads();

            unsigned colbits = __float_as_uint(BIGF);   // lane owns ref g0+lane

            for (int q0 = q_lo; q0 < q_hi; q0 += TB) {  // 1-2 passes typical
                int q = q0 + tid;                       // < NPAD always
                bool qa = q < q_hi;
                float4 vq = Q[q];
                float qu = qa ? vq.x : FARF;
                float qv = qa ? vq.y : FARF;
                float qz = qa ? vq.z : FARF;
                float rowmin = BIGF;

#pragma unroll
                for (int j = 0; j < 32; ++j) {
                    float4 y = tile[j];                 // uniform LDS.128 bcast
                    float d = fmaxf(fabsf(qu - y.x), fabsf(qv - y.y))
                            + fabsf(qz - y.z);
                    rowmin = fminf(rowmin, d);
                    unsigned red = __reduce_min_sync(0xffffffffu,
                                                     __float_as_uint(d));
                    if (lane == j) colbits = min(colbits, red);
                }
                if (qa) atomicMin(&Mx[q], __float_as_uint(rowmin));
            }

            int ridx = g0 + lane;
            if (ridx < r_hi) atomicMin(&My[ridx], colbits);
        }
    }

    // -------- hierarchical arrive (8 batch-tasks) --------
    __threadfence();
    __syncthreads();
    __shared__ int task_last;
    if (tid == 0)
        task_last = (atomicAdd(&g_done_task[b], 1u) == ARR - 1);
    __syncthreads();
    if (!task_last) return;

    // -------- per-batch tail: sum both min arrays --------
    __threadfence();
    {
        const uint4* __restrict__ p0 = (const uint4*)g_minbits[0][b];
        const uint4* __restrict__ p1 = (const uint4*)g_minbits[1][b];
        int nv = cnt >> 2;
        float s = 0.f;
        for (int k = tid; k < nv; k += TB) {
            uint4 u = p0[k], v = p1[k];
            s += (__uint_as_float(u.x) + __uint_as_float(u.y))
               + (__uint_as_float(u.z) + __uint_as_float(u.w));
            s += (__uint_as_float(v.x) + __uint_as_float(v.y))
               + (__uint_as_float(v.z) + __uint_as_float(v.w));
        }
        if (tid < (cnt & 3)) {
            int k = (cnt & ~3) + tid;
            s += __uint_as_float(g_minbits[0][b][k])
               + __uint_as_float(g_minbits[1][b][k]);
        }
        __shared__ float wsum[4];
#pragma unroll
        for (int o = 16; o > 0; o >>= 1) s += __shfl_down_sync(0xffffffffu, s, o);
        if (lane == 0) wsum[tid >> 5] = s;
        __syncthreads();
        if (tid == 0)
            g_tasksum[b] = (wsum[0] + wsum[1] + wsum[2] + wsum[3]) / (float)cnt;
    }

    // -------- global arrive; last batch-block combines --------
    __threadfence();
    __syncthreads();
    __shared__ int is_last;
    if (tid == 0)
        is_last = (atomicAdd(&g_done, 1u) == BB - 1);
    __syncthreads();
    if (!is_last) return;

    __threadfence();
    float l1p = g_l1part[tid];             // 128 partials, TB == 128
    __shared__ float wl[4];
#pragma unroll
    for (int o = 16; o > 0; o >>= 1) l1p += __shfl_down_sync(0xffffffffu, l1p, o);
    if (lane == 0) wl[tid >> 5] = l1p;
    __syncthreads();
    if (tid == 0) {
        float cdsum = 0.f;
#pragma unroll
        for (int t = 0; t < BB; ++t) cdsum += g_tasksum[t];
        float l1num = wl[0] + wl[1] + wl[2] + wl[3];
        int msum = 0;
#pragma unroll
        for (int bb = 0; bb < BB; ++bb) msum += g_cnt[bb];
        float l1 = l1num / 3.0f / (float)msum;
        float cd = cdsum / (float)BB;
        out[0] = l1 + expf(-l1) * cd;
        g_done = 0;                        // reset for next graph replay
    }
    __syncthreads();
    if (tid < BB) { g_cnt[tid] = 0; g_done_task[tid] = 0; }
}

// ---------------------------------------------------------------------------
extern "C" void kernel_launch(void* const* d_in, const int* in_sizes, int n_in,
                              void* d_out, int out_size) {
    const float* pred   = (const float*)d_in[0];
    const float* target = (const float*)d_in[1];
    const int*   mask   = (const int*)  d_in[2];
    const float* points = (const float*)d_in[3];
    float* out = (float*)d_out;

    prep_kernel<<<128, 128>>>(pred, target, mask, points);

    dim3 grid(GQ, RSPLIT, BB);   // (8, 32, 8) = 2048 blocks
    chamfer_kernel<<<grid, TB>>>(out);
}

// round 17
// speedup vs baseline: 1.2852x; 1.2852x over previous
#include <cuda_runtime.h>
#include <cuda_bf16.h>
#include <cuda_fp16.h>

#define BB 8
#define NN 2048
#define NPAD (NN + 512)
#define BIGF 1e30f
#define BIGH 60000.0f

// chamfer shape: TB=128, 4 packed queries/thread, grid (2, 32, 16) = 1024 blocks
#define TB     128
#define QPT    4
#define QSTEP  (QPT * TB)        // 512 query slots per pass
#define GQ     2
#define RSPLIT 32
#define GZ     (2 * BB)          // 16 tasks
#define ARR_PER_TASK (GQ * RSPLIT)   // 64 arrivals per task

// Scratch (allocation-free). Points transformed: (x+y, x-y, z, 0).
// g_valid[0]=clean(points+target), g_valid[1]=predp(points+pred)
// Pad region is zero-initialized at load and never written -> deterministic.
__device__ __align__(16) float4       g_valid[2][BB][NPAD];
__device__ __align__(16) unsigned int g_minbits[2][BB][NN];
__device__ int          g_cnt[BB];
__device__ float        g_l1part[128];
__device__ float        g_tasksum[GZ];
__device__ unsigned int g_done_task[GZ];
__device__ unsigned int g_done;

// ---------------------------------------------------------------------------
// Kernel 1: prep — 128 blocks x 128 threads, one point per thread (unchanged).
// ---------------------------------------------------------------------------
__global__ void __launch_bounds__(128)
prep_kernel(const float* __restrict__ pred,
            const float* __restrict__ target,
            const int*   __restrict__ mask,
            const float* __restrict__ points) {
    int bid = blockIdx.x, tid = threadIdx.x;
    int b = bid >> 4, s = bid & 15;
    int n  = s * 128 + tid;
    int gi = b * NN + n;

    const float* pp = pred   + gi * 3;
    const float* tt = target + gi * 3;
    const float* xx = points + gi * 3;
    float p0 = pp[0], p1 = pp[1], p2 = pp[2];
    float t0 = tt[0], t1 = tt[1], t2 = tt[2];
    float x0 = xx[0], x1 = xx[1], x2 = xx[2];
    int m = mask[gi];

    const unsigned bigbits = __float_as_uint(BIGF);
    g_minbits[0][b][n] = bigbits;
    g_minbits[1][b][n] = bigbits;

    float c0 = x0 + t0, c1 = x1 + t1, c2 = x2 + t2;   // clean
    float q0 = x0 + p0, q1 = x1 + p1, q2 = x2 + p2;   // predp
    float l1 = 0.f;

    __shared__ int sh_cnt, sh_base;
    if (tid == 0) sh_cnt = 0;
    __syncthreads();
    int klocal = -1;
    if (m) {
        l1 = fabsf(p0 - t0) + fabsf(p1 - t1) + fabsf(p2 - t2);
        klocal = atomicAdd(&sh_cnt, 1);
    }
    __syncthreads();
    if (tid == 0) sh_base = atomicAdd(&g_cnt[b], sh_cnt);

    __shared__ float wsum[4];
#pragma unroll
    for (int o = 16; o > 0; o >>= 1) l1 += __shfl_down_sync(0xffffffffu, l1, o);
    if ((tid & 31) == 0) wsum[tid >> 5] = l1;
    __syncthreads();
    if (tid == 0)
        g_l1part[bid] = wsum[0] + wsum[1] + wsum[2] + wsum[3];

    if (m) {
        int k = sh_base + klocal;
        g_valid[0][b][k] = make_float4(c0 + c1, c0 - c1, c2, 0.f);
        g_valid[1][b][k] = make_float4(q0 + q1, q0 - q1, q2, 0.f);
    }
}

// ---------------------------------------------------------------------------
// Kernel 2: half2 chamfer, grid (2, 32, 16) = 1024 blocks, TB=128.
// 4 queries/thread in 2 half2 regs; refs broadcast-packed (u,u)(v,v)(z,z).
// |dx|+|dy|+|dz| == max(|du|,|dv|) + |dz| with (u,v) = (x+y, x-y).
// ---------------------------------------------------------------------------
struct HRef { __half2 u, v; };     // one 8-byte LDS.64 per ref

__global__ void __launch_bounds__(TB)
chamfer_kernel(float* __restrict__ out) {
    int tid  = threadIdx.x;
    int task = blockIdx.z;
    int b    = task >> 1;
    int dir  = task & 1;               // 0: clean->pred, 1: pred->clean
    int cnt  = g_cnt[b];

    __shared__ HRef    tUV[32];
    __shared__ __half2 tZ[32];

    int qn   = (cnt + GQ - 1) / GQ;            // ~512
    int q_lo = blockIdx.x * qn;
    int q_hi = min(q_lo + qn, cnt);
    int rn   = (cnt + RSPLIT - 1) / RSPLIT;    // <= 64
    int r_lo = blockIdx.y * rn;
    int r_hi = min(r_lo + rn, cnt);

    if (q_lo < cnt && r_lo < r_hi) {
        const float4* __restrict__ Q = g_valid[dir][b];
        const float4* __restrict__ R = g_valid[dir ^ 1][b];
        unsigned int* __restrict__ M = g_minbits[dir][b];

        for (int g0 = r_lo; g0 < r_hi; g0 += 32) {       // 1 group typical
            __syncthreads();
            if (tid < 32) {
                int r = g0 + tid;
                float4 p = (r < r_hi) ? R[r]
                                      : make_float4(BIGH, BIGH, 0.f, 0.f);
                tUV[tid].u = __float2half2_rn(p.x);
                tUV[tid].v = __float2half2_rn(p.y);
                tZ[tid]    = __float2half2_rn(p.z);
            }
            __syncthreads();

            for (int q0b = q_lo; q0b < q_hi; q0b += QSTEP) {  // 1 pass typ.
                int qi0 = q0b + tid;       // unguarded: pad region is zeros
                int qi1 = qi0 + TB;
                int qi2 = qi0 + 2 * TB;
                int qi3 = qi0 + 3 * TB;
                float4 v0 = Q[qi0], v1 = Q[qi1], v2 = Q[qi2], v3 = Q[qi3];
                __half2 quA = __floats2half2_rn(v0.x, v1.x);
                __half2 qvA = __floats2half2_rn(v0.y, v1.y);
                __half2 qzA = __floats2half2_rn(v0.z, v1.z);
                __half2 quB = __floats2half2_rn(v2.x, v3.x);
                __half2 qvB = __floats2half2_rn(v2.y, v3.y);
                __half2 qzB = __floats2half2_rn(v2.z, v3.z);
                __half2 mnA = __float2half2_rn(BIGH);
                __half2 mnB = mnA;

#pragma unroll
                for (int j = 0; j < 32; ++j) {
                    __half2 yu = tUV[j].u, yv = tUV[j].v, yz = tZ[j];
                    __half2 duA = __hsub2(quA, yu);
                    __half2 dvA = __hsub2(qvA, yv);
                    __half2 dzA = __hsub2(qzA, yz);
                    __half2 dA  = __hadd2(__hmax2(__habs2(duA), __habs2(dvA)),
                                          __habs2(dzA));
                    mnA = __hmin2(mnA, dA);
                    __half2 duB = __hsub2(quB, yu);
                    __half2 dvB = __hsub2(qvB, yv);
                    __half2 dzB = __hsub2(qzB, yz);
                    __half2 dB  = __hadd2(__hmax2(__habs2(duB), __habs2(dvB)),
                                          __habs2(dzB));
                    mnB = __hmin2(mnB, dB);
                }

                float m0 = __low2float(mnA), m1 = __high2float(mnA);
                float m2 = __low2float(mnB), m3 = __high2float(mnB);
                if (qi0 < q_hi) atomicMin(&M[qi0], __float_as_uint(m0));
                if (qi1 < q_hi) atomicMin(&M[qi1], __float_as_uint(m1));
                if (qi2 < q_hi) atomicMin(&M[qi2], __float_as_uint(m2));
                if (qi3 < q_hi) atomicMin(&M[qi3], __float_as_uint(m3));
            }
        }
    }

    // -------- hierarchical arrive --------
    __threadfence();
    __syncthreads();
    __shared__ int task_last;
    if (tid == 0)
        task_last = (atomicAdd(&g_done_task[task], 1u) == ARR_PER_TASK - 1);
    __syncthreads();
    if (!task_last) return;

    // -------- per-task tail: reduce this (dir,b) min array --------
    __threadfence();
    {
        const uint4* __restrict__ p = (const uint4*)g_minbits[dir][b];
        int nv = cnt >> 2;
        float s = 0.f;
        for (int k = tid; k < nv; k += TB) {
            uint4 u = p[k];
            s += (__uint_as_float(u.x) + __uint_as_float(u.y))
               + (__uint_as_float(u.z) + __uint_as_float(u.w));
        }
        if (tid < (cnt & 3))
            s += __uint_as_float(g_minbits[dir][b][(cnt & ~3) + tid]);

        __shared__ float wsum[4];
#pragma unroll
        for (int o = 16; o > 0; o >>= 1) s += __shfl_down_sync(0xffffffffu, s, o);
        if ((tid & 31) == 0) wsum[tid >> 5] = s;
        __syncthreads();
        if (tid == 0)
            g_tasksum[task] = wsum[0] + wsum[1] + wsum[2] + wsum[3];
    }

    // -------- global arrive; last task-block combines --------
    __threadfence();
    __syncthreads();
    __shared__ int is_last;
    if (tid == 0)
        is_last = (atomicAdd(&g_done, 1u) == GZ - 1);
    __syncthreads();
    if (!is_last) return;

    __threadfence();
    float l1p = g_l1part[tid];             // 128 partials, TB == 128
    __shared__ float wl[4];
#pragma unroll
    for (int o = 16; o > 0; o >>= 1) l1p += __shfl_down_sync(0xffffffffu, l1p, o);
    if ((tid & 31) == 0) wl[tid >> 5] = l1p;
    __syncthreads();
    if (tid == 0) {
        float cdsum = 0.f;
#pragma unroll
        for (int t = 0; t < GZ; ++t)
            cdsum += g_tasksum[t] / (float)g_cnt[t >> 1];
        float l1num = wl[0] + wl[1] + wl[2] + wl[3];
        int msum = 0;
#pragma unroll
        for (int bb = 0; bb < BB; ++bb) msum += g_cnt[bb];
        float l1 = l1num / 3.0f / (float)msum;
        float cd = cdsum / (float)BB;
        out[0] = l1 + expf(-l1) * cd;
        g_done = 0;                        // reset for next graph replay
    }
    __syncthreads();
    if (tid < BB)  g_cnt[tid] = 0;
    if (tid < GZ)  g_done_task[tid] = 0;
}

// ---------------------------------------------------------------------------
extern "C" void kernel_launch(void* const* d_in, const int* in_sizes, int n_in,
                              void* d_out, int out_size) {
    const float* pred   = (const float*)d_in[0];
    const float* target = (const float*)d_in[1];
    const int*   mask   = (const int*)  d_in[2];
    const float* points = (const float*)d_in[3];
    float* out = (float*)d_out;

    prep_kernel<<<128, 128>>>(pred, target, mask, points);

    dim3 grid(GQ, RSPLIT, GZ);   // (2, 32, 16) = 1024 blocks
    chamfer_kernel<<<grid, TB>>>(out);
}